// round 1
// baseline (speedup 1.0000x reference)
#include <cuda_runtime.h>
#include <math.h>

// Problem constants
constexpr int B  = 8;
constexpr int S  = 1024;
constexpr int D  = 512;
constexpr int H  = 8;
constexpr int DH = 64;

// Scratch: projected heads [B,H,S,DH] each, and attention output X [B,H,S,DH].
// X's contiguous (B,H,S,DH) layout reinterpreted as (B, 1024, 512) is exactly
// the reference's reshape(B, S, H*DH) (no transpose), since H*S*DH = 1024*512.
__device__ float g_Qh[B * H * S * DH];
__device__ float g_Kh[B * H * S * DH];
__device__ float g_Vh[B * H * S * DH];
__device__ float g_X [B * H * S * DH];

// ---------------------------------------------------------------------------
// Kernel 1: fused QKV per-head projection.
//   Out[b,h,s,e] = sum_k In[b,s,k] * W[h,k,e] + bias[h,e]
// grid = (S/64, B*H, 3), block = 256 (16x16 -> 4x4 register tile of 64x64)
// ---------------------------------------------------------------------------
__global__ void proj_kernel(const float* __restrict__ Q,
                            const float* __restrict__ K,
                            const float* __restrict__ V,
                            const float* __restrict__ Wq, const float* __restrict__ bq,
                            const float* __restrict__ Wk, const float* __restrict__ bk,
                            const float* __restrict__ Wv, const float* __restrict__ bv)
{
    const int p  = blockIdx.z;           // 0 = Q, 1 = K, 2 = V
    const int bh = blockIdx.y;
    const int b  = bh >> 3;
    const int h  = bh & 7;
    const int s0 = blockIdx.x * 64;

    const float* In   = (p == 0) ? Q  : (p == 1) ? K  : V;
    const float* W    = (p == 0) ? Wq : (p == 1) ? Wk : Wv;
    const float* bias = (p == 0) ? bq : (p == 1) ? bk : bv;
    float*       Out  = (p == 0) ? g_Qh : (p == 1) ? g_Kh : g_Vh;

    __shared__ float As[64][33];  // [row][k]
    __shared__ float Bs[32][65];  // [k][col]

    const int tid = threadIdx.x;
    const int tx  = tid & 15;
    const int ty  = tid >> 4;

    float acc[4][4] = {};

    const float* Ab = In + ((size_t)b * S + s0) * D;
    const float* Wb = W + (size_t)h * D * DH;

    for (int kk = 0; kk < D; kk += 32) {
        #pragma unroll
        for (int l = 0; l < 8; l++) {            // 64x32 A tile
            int idx = tid + l * 256;
            int i = idx >> 5, k = idx & 31;
            As[i][k] = Ab[(size_t)i * D + kk + k];
        }
        #pragma unroll
        for (int l = 0; l < 8; l++) {            // 32x64 W tile
            int idx = tid + l * 256;
            int k = idx >> 6, j = idx & 63;
            Bs[k][j] = Wb[(size_t)(kk + k) * DH + j];
        }
        __syncthreads();
        #pragma unroll
        for (int k = 0; k < 32; k++) {
            float a[4], w[4];
            #pragma unroll
            for (int ii = 0; ii < 4; ii++) a[ii] = As[ty * 4 + ii][k];
            #pragma unroll
            for (int jj = 0; jj < 4; jj++) w[jj] = Bs[k][tx * 4 + jj];
            #pragma unroll
            for (int ii = 0; ii < 4; ii++)
                #pragma unroll
                for (int jj = 0; jj < 4; jj++)
                    acc[ii][jj] += a[ii] * w[jj];
        }
        __syncthreads();
    }

    float* Ob = Out + (((size_t)b * H + h) * S + s0) * DH;
    #pragma unroll
    for (int ii = 0; ii < 4; ii++) {
        int i = ty * 4 + ii;
        #pragma unroll
        for (int jj = 0; jj < 4; jj++) {
            int j = tx * 4 + jj;
            Ob[(size_t)i * DH + j] = acc[ii][jj] + bias[h * DH + j];
        }
    }
}

// ---------------------------------------------------------------------------
// Kernel 2: flash-attention per (b, h, q-tile of 64 rows).
// Online softmax over 16 KV tiles of 64 rows. grid = (S/64, B*H), block = 256.
// Dynamic smem: Qs, Ks, Vs, Ps each 64x65 floats = 66,560 B.
// ---------------------------------------------------------------------------
__global__ void attn_kernel()
{
    const int bh = blockIdx.y;
    const int b  = bh >> 3;
    const int h  = bh & 7;
    const int q0 = blockIdx.x * 64;

    extern __shared__ float sm[];
    float* Qs = sm;                 // [64][65]
    float* Ks = Qs + 64 * 65;
    float* Vs = Ks + 64 * 65;
    float* Ps = Vs + 64 * 65;

    const int tid = threadIdx.x;
    const int tx  = tid & 15;
    const int ty  = tid >> 4;

    const float scale = 0.125f;     // 1/sqrt(64)

    const float* Qb = g_Qh + (((size_t)b * H + h) * S + q0) * DH;
    const float* Kb = g_Kh + (((size_t)b * H + h) * S) * DH;
    const float* Vb = g_Vh + (((size_t)b * H + h) * S) * DH;

    // Load Q tile once, folding in the softmax scale.
    #pragma unroll
    for (int l = 0; l < 16; l++) {
        int idx = tid + l * 256;       // 0..4095
        int i = idx >> 6, e = idx & 63;
        Qs[i * 65 + e] = Qb[(size_t)i * DH + e] * scale;
    }

    float m[4], lsum[4];
    float O[4][4] = {};
    #pragma unroll
    for (int ii = 0; ii < 4; ii++) { m[ii] = -INFINITY; lsum[ii] = 0.f; }

    for (int kv = 0; kv < S / 64; kv++) {
        const float* Kt = Kb + (size_t)kv * 64 * DH;
        const float* Vt = Vb + (size_t)kv * 64 * DH;
        #pragma unroll
        for (int l = 0; l < 16; l++) {
            int idx = tid + l * 256;
            int i = idx >> 6, e = idx & 63;
            Ks[i * 65 + e] = Kt[(size_t)i * DH + e];
            Vs[i * 65 + e] = Vt[(size_t)i * DH + e];
        }
        __syncthreads();

        // scores s[ii][jj] = Q[row] . K[col]
        float s[4][4] = {};
        #pragma unroll 8
        for (int e = 0; e < 64; e++) {
            float a[4], w[4];
            #pragma unroll
            for (int ii = 0; ii < 4; ii++) a[ii] = Qs[(ty * 4 + ii) * 65 + e];
            #pragma unroll
            for (int jj = 0; jj < 4; jj++) w[jj] = Ks[(tx * 4 + jj) * 65 + e];
            #pragma unroll
            for (int ii = 0; ii < 4; ii++)
                #pragma unroll
                for (int jj = 0; jj < 4; jj++)
                    s[ii][jj] += a[ii] * w[jj];
        }

        // online softmax update per row (16 lanes of same ty own one row group)
        #pragma unroll
        for (int ii = 0; ii < 4; ii++) {
            float mx = s[ii][0];
            #pragma unroll
            for (int jj = 1; jj < 4; jj++) mx = fmaxf(mx, s[ii][jj]);
            #pragma unroll
            for (int off = 8; off >= 1; off >>= 1)
                mx = fmaxf(mx, __shfl_xor_sync(0xffffffffu, mx, off));
            float mnew  = fmaxf(m[ii], mx);
            float alpha = __expf(m[ii] - mnew);
            m[ii] = mnew;
            float rs = 0.f;
            #pragma unroll
            for (int jj = 0; jj < 4; jj++) {
                s[ii][jj] = __expf(s[ii][jj] - mnew);
                rs += s[ii][jj];
            }
            #pragma unroll
            for (int off = 8; off >= 1; off >>= 1)
                rs += __shfl_xor_sync(0xffffffffu, rs, off);
            lsum[ii] = lsum[ii] * alpha + rs;
            #pragma unroll
            for (int jj = 0; jj < 4; jj++) O[ii][jj] *= alpha;
            #pragma unroll
            for (int jj = 0; jj < 4; jj++)
                Ps[(ty * 4 + ii) * 65 + tx * 4 + jj] = s[ii][jj];
        }
        __syncthreads();

        // O += P @ V
        #pragma unroll 8
        for (int c = 0; c < 64; c++) {
            float pr[4], v[4];
            #pragma unroll
            for (int ii = 0; ii < 4; ii++) pr[ii] = Ps[(ty * 4 + ii) * 65 + c];
            #pragma unroll
            for (int jj = 0; jj < 4; jj++) v[jj] = Vs[c * 65 + tx * 4 + jj];
            #pragma unroll
            for (int ii = 0; ii < 4; ii++)
                #pragma unroll
                for (int jj = 0; jj < 4; jj++)
                    O[ii][jj] += pr[ii] * v[jj];
        }
        __syncthreads();
    }

    float* Xb = g_X + (((size_t)b * H + h) * S + q0) * DH;
    #pragma unroll
    for (int ii = 0; ii < 4; ii++) {
        float inv = 1.0f / lsum[ii];
        #pragma unroll
        for (int jj = 0; jj < 4; jj++)
            Xb[(size_t)(ty * 4 + ii) * DH + tx * 4 + jj] = O[ii][jj] * inv;
    }
}

// ---------------------------------------------------------------------------
// Kernel 3: output projection.
// g_X viewed as [B][1024][512] (== reference's reshape) @ Wo[512,512] + bo.
// grid = (512/64, 1024/64, B), block = 256.
// ---------------------------------------------------------------------------
__global__ void oproj_kernel(const float* __restrict__ Wo,
                             const float* __restrict__ bo,
                             float* __restrict__ out)
{
    const int b  = blockIdx.z;
    const int m0 = blockIdx.y * 64;
    const int n0 = blockIdx.x * 64;

    __shared__ float As[64][33];
    __shared__ float Bs[32][65];

    const int tid = threadIdx.x;
    const int tx  = tid & 15;
    const int ty  = tid >> 4;

    float acc[4][4] = {};

    const float* Ab = g_X + (size_t)b * 1024 * 512 + (size_t)m0 * 512;

    for (int kk = 0; kk < 512; kk += 32) {
        #pragma unroll
        for (int l = 0; l < 8; l++) {
            int idx = tid + l * 256;
            int i = idx >> 5, k = idx & 31;
            As[i][k] = Ab[(size_t)i * 512 + kk + k];
        }
        #pragma unroll
        for (int l = 0; l < 8; l++) {
            int idx = tid + l * 256;
            int k = idx >> 6, j = idx & 63;
            Bs[k][j] = Wo[(size_t)(kk + k) * 512 + n0 + j];
        }
        __syncthreads();
        #pragma unroll
        for (int k = 0; k < 32; k++) {
            float a[4], w[4];
            #pragma unroll
            for (int ii = 0; ii < 4; ii++) a[ii] = As[ty * 4 + ii][k];
            #pragma unroll
            for (int jj = 0; jj < 4; jj++) w[jj] = Bs[k][tx * 4 + jj];
            #pragma unroll
            for (int ii = 0; ii < 4; ii++)
                #pragma unroll
                for (int jj = 0; jj < 4; jj++)
                    acc[ii][jj] += a[ii] * w[jj];
        }
        __syncthreads();
    }

    float* Ob = out + (size_t)b * 1024 * 512 + (size_t)m0 * 512 + n0;
    #pragma unroll
    for (int ii = 0; ii < 4; ii++) {
        int i = ty * 4 + ii;
        #pragma unroll
        for (int jj = 0; jj < 4; jj++) {
            int j = tx * 4 + jj;
            Ob[(size_t)i * 512 + j] = acc[ii][jj] + bo[n0 + j];
        }
    }
}

// ---------------------------------------------------------------------------
extern "C" void kernel_launch(void* const* d_in, const int* in_sizes, int n_in,
                              void* d_out, int out_size)
{
    const float* Q  = (const float*)d_in[0];
    const float* K  = (const float*)d_in[1];
    const float* V  = (const float*)d_in[2];
    const float* Wq = (const float*)d_in[3];
    const float* bq = (const float*)d_in[4];
    const float* Wk = (const float*)d_in[5];
    const float* bk = (const float*)d_in[6];
    const float* Wv = (const float*)d_in[7];
    const float* bv = (const float*)d_in[8];
    const float* Wo = (const float*)d_in[9];
    const float* bo = (const float*)d_in[10];
    float* out = (float*)d_out;

    // 1) QKV projections
    dim3 g1(S / 64, B * H, 3);
    proj_kernel<<<g1, 256>>>(Q, K, V, Wq, bq, Wk, bk, Wv, bv);

    // 2) attention (needs 66,560 B dynamic smem)
    const int attn_smem = 4 * 64 * 65 * (int)sizeof(float);
    cudaFuncSetAttribute(attn_kernel,
                         cudaFuncAttributeMaxDynamicSharedMemorySize, attn_smem);
    dim3 g2(S / 64, B * H);
    attn_kernel<<<g2, 256, attn_smem>>>();

    // 3) output projection
    dim3 g3(512 / 64, 1024 / 64, B);
    oproj_kernel<<<g3, 256>>>(Wo, bo, out);
}

// round 3
// speedup vs baseline: 1.5727x; 1.5727x over previous
#include <cuda_runtime.h>
#include <cuda_bf16.h>
#include <math.h>
#include <stdint.h>

// ---------------------------------------------------------------------------
// Problem constants
// ---------------------------------------------------------------------------
constexpr int B  = 8;
constexpr int S  = 1024;
constexpr int D  = 512;
constexpr int H  = 8;
constexpr int DH = 64;

// ---------------------------------------------------------------------------
// Device scratch
// ---------------------------------------------------------------------------
__device__ float g_Qh[B * H * S * DH];
__device__ float g_Kh[B * H * S * DH];
__device__ float g_Vh[B * H * S * DH];
__device__ float g_X [B * H * S * DH];

// Pre-transposed, bf16-split weight planes: [n][k] layout (k contiguous, ld=512)
__device__ __nv_bfloat16 g_Wt_hi [3 * H * DH * D];
__device__ __nv_bfloat16 g_Wt_lo [3 * H * DH * D];
__device__ __nv_bfloat16 g_Wot_hi[D * D];
__device__ __nv_bfloat16 g_Wot_lo[D * D];

// ---------------------------------------------------------------------------
// bf16 HMMA: D(f32) += A(bf16,row) * B(bf16,col)   m16n8k16
// ---------------------------------------------------------------------------
__device__ __forceinline__ void mma_bf16(float* d, const uint32_t* a, const uint32_t* b) {
    asm volatile(
        "mma.sync.aligned.m16n8k16.row.col.f32.bf16.bf16.f32 "
        "{%0,%1,%2,%3}, {%4,%5,%6,%7}, {%8,%9}, {%0,%1,%2,%3};"
        : "+f"(d[0]), "+f"(d[1]), "+f"(d[2]), "+f"(d[3])
        : "r"(a[0]), "r"(a[1]), "r"(a[2]), "r"(a[3]), "r"(b[0]), "r"(b[1]));
}

// ---------------------------------------------------------------------------
// Weight prep: transpose + bf16 split
// ---------------------------------------------------------------------------
__global__ void prep_weights(const float* __restrict__ Wq,
                             const float* __restrict__ Wk,
                             const float* __restrict__ Wv,
                             const float* __restrict__ Wo)
{
    int idx = blockIdx.x * blockDim.x + threadIdx.x;   // 0 .. 1048575
    if (idx < 3 * H * DH * D) {
        int k = idx & 511;
        int e = (idx >> 9) & 63;
        int h = (idx >> 15) & 7;
        int p = idx >> 18;
        const float* W = (p == 0) ? Wq : (p == 1) ? Wk : Wv;
        float v = W[h * (D * DH) + k * DH + e];
        __nv_bfloat16 hi = __float2bfloat16(v);
        __nv_bfloat16 lo = __float2bfloat16(v - __bfloat162float(hi));
        g_Wt_hi[idx] = hi;
        g_Wt_lo[idx] = lo;
    } else {
        int j = idx - 3 * H * DH * D;                  // 0 .. 262143
        int k = j & 511;
        int n = j >> 9;
        float v = Wo[k * 512 + n];
        __nv_bfloat16 hi = __float2bfloat16(v);
        __nv_bfloat16 lo = __float2bfloat16(v - __bfloat162float(hi));
        g_Wot_hi[j] = hi;
        g_Wot_lo[j] = lo;
    }
}

// ---------------------------------------------------------------------------
// Shared GEMM body: Out[128,64] = A[128,512](f32) * B[64,512](bf16 hi/lo)^T + bias
// Block = 256 threads (8 warps; warp tile 32x32). Smem layout (bf16, row pad 8):
//   As_hi[128][72], As_lo[128][72], Bs_hi[64][72], Bs_lo[64][72]  -> 55296 B
// ---------------------------------------------------------------------------
constexpr int LDS_PAD = 72;
constexpr int GEMM_SMEM = (128 * LDS_PAD * 2 + 64 * LDS_PAD * 2) * 2;  // 55296

__device__ __forceinline__ void gemm_128x64_split(
    const float* __restrict__ A, int ldA,
    const __nv_bfloat16* __restrict__ Bh_g,
    const __nv_bfloat16* __restrict__ Bl_g,
    const float* __restrict__ bias,     // 64-wide slice
    float* __restrict__ Out, int ldOut,
    char* smem)
{
    __nv_bfloat16* As_hi = reinterpret_cast<__nv_bfloat16*>(smem);
    __nv_bfloat16* As_lo = As_hi + 128 * LDS_PAD;
    __nv_bfloat16* Bs_hi = As_lo + 128 * LDS_PAD;
    __nv_bfloat16* Bs_lo = Bs_hi + 64 * LDS_PAD;

    const int tid  = threadIdx.x;
    const int wid  = tid >> 5;
    const int lane = tid & 31;
    const int g    = lane >> 2;      // 0..7
    const int t    = lane & 3;       // 0..3
    const int m0   = (wid >> 1) * 32;
    const int n0w  = (wid & 1) * 32;

    float acc[2][4][4];
    #pragma unroll
    for (int mf = 0; mf < 2; mf++)
        #pragma unroll
        for (int nf = 0; nf < 4; nf++)
            #pragma unroll
            for (int r = 0; r < 4; r++) acc[mf][nf][r] = 0.f;

    for (int c = 0; c < 8; c++) {
        const int kk = c * 64;

        // ---- load A chunk (128x64 f32 -> bf16 hi/lo) ----
        #pragma unroll
        for (int i = 0; i < 8; i++) {
            int idx = tid + i * 256;          // 0..2047
            int row = idx >> 4, c4 = idx & 15;
            float4 v = *reinterpret_cast<const float4*>(A + (size_t)row * ldA + kk + c4 * 4);
            __nv_bfloat16 h0 = __float2bfloat16(v.x);
            __nv_bfloat16 h1 = __float2bfloat16(v.y);
            __nv_bfloat16 h2 = __float2bfloat16(v.z);
            __nv_bfloat16 h3 = __float2bfloat16(v.w);
            __nv_bfloat16 l0 = __float2bfloat16(v.x - __bfloat162float(h0));
            __nv_bfloat16 l1 = __float2bfloat16(v.y - __bfloat162float(h1));
            __nv_bfloat16 l2 = __float2bfloat16(v.z - __bfloat162float(h2));
            __nv_bfloat16 l3 = __float2bfloat16(v.w - __bfloat162float(h3));
            __nv_bfloat162 hp0 = __halves2bfloat162(h0, h1);
            __nv_bfloat162 hp1 = __halves2bfloat162(h2, h3);
            __nv_bfloat162 lp0 = __halves2bfloat162(l0, l1);
            __nv_bfloat162 lp1 = __halves2bfloat162(l2, l3);
            uint2 hw = make_uint2(*reinterpret_cast<uint32_t*>(&hp0),
                                  *reinterpret_cast<uint32_t*>(&hp1));
            uint2 lw = make_uint2(*reinterpret_cast<uint32_t*>(&lp0),
                                  *reinterpret_cast<uint32_t*>(&lp1));
            *reinterpret_cast<uint2*>(As_hi + row * LDS_PAD + c4 * 4) = hw;
            *reinterpret_cast<uint2*>(As_lo + row * LDS_PAD + c4 * 4) = lw;
        }

        // ---- load B chunk (64x64 bf16 x2 planes) ----
        #pragma unroll
        for (int i = 0; i < 2; i++) {
            int idx = tid + i * 256;          // 0..511
            int n = idx >> 3, q = idx & 7;
            *reinterpret_cast<uint4*>(Bs_hi + n * LDS_PAD + q * 8) =
                *reinterpret_cast<const uint4*>(Bh_g + (size_t)n * 512 + kk + q * 8);
            *reinterpret_cast<uint4*>(Bs_lo + n * LDS_PAD + q * 8) =
                *reinterpret_cast<const uint4*>(Bl_g + (size_t)n * 512 + kk + q * 8);
        }
        __syncthreads();

        // ---- compute: 4 k-steps of 16 ----
        #pragma unroll
        for (int ks = 0; ks < 4; ks++) {
            uint32_t ah[2][4], al[2][4];
            #pragma unroll
            for (int mf = 0; mf < 2; mf++) {
                int base = (m0 + mf * 16 + g) * LDS_PAD + ks * 16 + t * 2;
                ah[mf][0] = *reinterpret_cast<const uint32_t*>(As_hi + base);
                ah[mf][1] = *reinterpret_cast<const uint32_t*>(As_hi + base + 8 * LDS_PAD);
                ah[mf][2] = *reinterpret_cast<const uint32_t*>(As_hi + base + 8);
                ah[mf][3] = *reinterpret_cast<const uint32_t*>(As_hi + base + 8 * LDS_PAD + 8);
                al[mf][0] = *reinterpret_cast<const uint32_t*>(As_lo + base);
                al[mf][1] = *reinterpret_cast<const uint32_t*>(As_lo + base + 8 * LDS_PAD);
                al[mf][2] = *reinterpret_cast<const uint32_t*>(As_lo + base + 8);
                al[mf][3] = *reinterpret_cast<const uint32_t*>(As_lo + base + 8 * LDS_PAD + 8);
            }
            uint32_t bh[4][2], bl[4][2];
            #pragma unroll
            for (int nf = 0; nf < 4; nf++) {
                int base = (n0w + nf * 8 + g) * LDS_PAD + ks * 16 + t * 2;
                bh[nf][0] = *reinterpret_cast<const uint32_t*>(Bs_hi + base);
                bh[nf][1] = *reinterpret_cast<const uint32_t*>(Bs_hi + base + 8);
                bl[nf][0] = *reinterpret_cast<const uint32_t*>(Bs_lo + base);
                bl[nf][1] = *reinterpret_cast<const uint32_t*>(Bs_lo + base + 8);
            }
            #pragma unroll
            for (int mf = 0; mf < 2; mf++)
                #pragma unroll
                for (int nf = 0; nf < 4; nf++) {
                    mma_bf16(acc[mf][nf], ah[mf], bh[nf]);
                    mma_bf16(acc[mf][nf], ah[mf], bl[nf]);
                    mma_bf16(acc[mf][nf], al[mf], bh[nf]);
                }
        }
        __syncthreads();
    }

    // ---- epilogue ----
    #pragma unroll
    for (int mf = 0; mf < 2; mf++) {
        #pragma unroll
        for (int nf = 0; nf < 4; nf++) {
            int row = m0 + mf * 16 + g;
            int col = n0w + nf * 8 + t * 2;
            float b0 = bias[col], b1 = bias[col + 1];
            float2 v0 = make_float2(acc[mf][nf][0] + b0, acc[mf][nf][1] + b1);
            float2 v1 = make_float2(acc[mf][nf][2] + b0, acc[mf][nf][3] + b1);
            *reinterpret_cast<float2*>(Out + (size_t)row * ldOut + col) = v0;
            *reinterpret_cast<float2*>(Out + (size_t)(row + 8) * ldOut + col) = v1;
        }
    }
}

// ---------------------------------------------------------------------------
// QKV projection on HMMA: grid (S/128, B*H, 3), block 256
// ---------------------------------------------------------------------------
__global__ void __launch_bounds__(256)
proj_mma(const float* __restrict__ Q, const float* __restrict__ K,
         const float* __restrict__ V,
         const float* __restrict__ bq, const float* __restrict__ bk,
         const float* __restrict__ bv)
{
    extern __shared__ char smem[];
    const int p  = blockIdx.z;
    const int bh = blockIdx.y;
    const int b  = bh >> 3, h = bh & 7;
    const int s0 = blockIdx.x * 128;

    const float* In   = (p == 0) ? Q : (p == 1) ? K : V;
    const float* bias = ((p == 0) ? bq : (p == 1) ? bk : bv) + h * DH;
    float* Out = ((p == 0) ? g_Qh : (p == 1) ? g_Kh : g_Vh)
                 + (((size_t)b * H + h) * S + s0) * DH;

    gemm_128x64_split(In + ((size_t)b * S + s0) * D, D,
                      g_Wt_hi + (size_t)(p * H + h) * DH * D,
                      g_Wt_lo + (size_t)(p * H + h) * DH * D,
                      bias, Out, DH, smem);
}

// ---------------------------------------------------------------------------
// Output projection on HMMA: grid (512/64, 1024/128, B), block 256
// ---------------------------------------------------------------------------
__global__ void __launch_bounds__(256)
oproj_mma(const float* __restrict__ bo, float* __restrict__ out)
{
    extern __shared__ char smem[];
    const int b  = blockIdx.z;
    const int m0 = blockIdx.y * 128;
    const int n0 = blockIdx.x * 64;

    gemm_128x64_split(g_X + (size_t)b * 1024 * 512 + (size_t)m0 * 512, 512,
                      g_Wot_hi + (size_t)n0 * D,
                      g_Wot_lo + (size_t)n0 * D,
                      bo + n0,
                      out + (size_t)b * 1024 * 512 + (size_t)m0 * 512 + n0, 512,
                      smem);
}

// ---------------------------------------------------------------------------
// Flash attention (fp32 FFMA — next round's target)
// ---------------------------------------------------------------------------
__global__ void attn_kernel()
{
    const int bh = blockIdx.y;
    const int b  = bh >> 3;
    const int h  = bh & 7;
    const int q0 = blockIdx.x * 64;

    extern __shared__ float sm[];
    float* Qs = sm;
    float* Ks = Qs + 64 * 65;
    float* Vs = Ks + 64 * 65;
    float* Ps = Vs + 64 * 65;

    const int tid = threadIdx.x;
    const int tx  = tid & 15;
    const int ty  = tid >> 4;

    const float scale = 0.125f;

    const float* Qb = g_Qh + (((size_t)b * H + h) * S + q0) * DH;
    const float* Kb = g_Kh + (((size_t)b * H + h) * S) * DH;
    const float* Vb = g_Vh + (((size_t)b * H + h) * S) * DH;

    #pragma unroll
    for (int l = 0; l < 16; l++) {
        int idx = tid + l * 256;
        int i = idx >> 6, e = idx & 63;
        Qs[i * 65 + e] = Qb[(size_t)i * DH + e] * scale;
    }

    float m[4], lsum[4];
    float O[4][4] = {};
    #pragma unroll
    for (int ii = 0; ii < 4; ii++) { m[ii] = -INFINITY; lsum[ii] = 0.f; }

    for (int kv = 0; kv < S / 64; kv++) {
        const float* Kt = Kb + (size_t)kv * 64 * DH;
        const float* Vt = Vb + (size_t)kv * 64 * DH;
        #pragma unroll
        for (int l = 0; l < 16; l++) {
            int idx = tid + l * 256;
            int i = idx >> 6, e = idx & 63;
            Ks[i * 65 + e] = Kt[(size_t)i * DH + e];
            Vs[i * 65 + e] = Vt[(size_t)i * DH + e];
        }
        __syncthreads();

        float s[4][4] = {};
        #pragma unroll 8
        for (int e = 0; e < 64; e++) {
            float a[4], w[4];
            #pragma unroll
            for (int ii = 0; ii < 4; ii++) a[ii] = Qs[(ty * 4 + ii) * 65 + e];
            #pragma unroll
            for (int jj = 0; jj < 4; jj++) w[jj] = Ks[(tx * 4 + jj) * 65 + e];
            #pragma unroll
            for (int ii = 0; ii < 4; ii++)
                #pragma unroll
                for (int jj = 0; jj < 4; jj++)
                    s[ii][jj] += a[ii] * w[jj];
        }

        #pragma unroll
        for (int ii = 0; ii < 4; ii++) {
            float mx = s[ii][0];
            #pragma unroll
            for (int jj = 1; jj < 4; jj++) mx = fmaxf(mx, s[ii][jj]);
            #pragma unroll
            for (int off = 8; off >= 1; off >>= 1)
                mx = fmaxf(mx, __shfl_xor_sync(0xffffffffu, mx, off));
            float mnew  = fmaxf(m[ii], mx);
            float alpha = __expf(m[ii] - mnew);
            m[ii] = mnew;
            float rs = 0.f;
            #pragma unroll
            for (int jj = 0; jj < 4; jj++) {
                s[ii][jj] = __expf(s[ii][jj] - mnew);
                rs += s[ii][jj];
            }
            #pragma unroll
            for (int off = 8; off >= 1; off >>= 1)
                rs += __shfl_xor_sync(0xffffffffu, rs, off);
            lsum[ii] = lsum[ii] * alpha + rs;
            #pragma unroll
            for (int jj = 0; jj < 4; jj++) O[ii][jj] *= alpha;
            #pragma unroll
            for (int jj = 0; jj < 4; jj++)
                Ps[(ty * 4 + ii) * 65 + tx * 4 + jj] = s[ii][jj];
        }
        __syncthreads();

        #pragma unroll 8
        for (int c = 0; c < 64; c++) {
            float pr[4], v[4];
            #pragma unroll
            for (int ii = 0; ii < 4; ii++) pr[ii] = Ps[(ty * 4 + ii) * 65 + c];
            #pragma unroll
            for (int jj = 0; jj < 4; jj++) v[jj] = Vs[c * 65 + tx * 4 + jj];
            #pragma unroll
            for (int ii = 0; ii < 4; ii++)
                #pragma unroll
                for (int jj = 0; jj < 4; jj++)
                    O[ii][jj] += pr[ii] * v[jj];
        }
        __syncthreads();
    }

    float* Xb = g_X + (((size_t)b * H + h) * S + q0) * DH;
    #pragma unroll
    for (int ii = 0; ii < 4; ii++) {
        float inv = 1.0f / lsum[ii];
        #pragma unroll
        for (int jj = 0; jj < 4; jj++)
            Xb[(size_t)(ty * 4 + ii) * DH + tx * 4 + jj] = O[ii][jj] * inv;
    }
}

// ---------------------------------------------------------------------------
extern "C" void kernel_launch(void* const* d_in, const int* in_sizes, int n_in,
                              void* d_out, int out_size)
{
    const float* Q  = (const float*)d_in[0];
    const float* K  = (const float*)d_in[1];
    const float* V  = (const float*)d_in[2];
    const float* Wq = (const float*)d_in[3];
    const float* bq = (const float*)d_in[4];
    const float* Wk = (const float*)d_in[5];
    const float* bk = (const float*)d_in[6];
    const float* Wv = (const float*)d_in[7];
    const float* bv = (const float*)d_in[8];
    const float* Wo = (const float*)d_in[9];
    const float* bo = (const float*)d_in[10];
    float* out = (float*)d_out;

    // 0) weight transpose + bf16 split
    prep_weights<<<4096, 256>>>(Wq, Wk, Wv, Wo);

    // 1) QKV projections on HMMA
    cudaFuncSetAttribute(proj_mma, cudaFuncAttributeMaxDynamicSharedMemorySize, GEMM_SMEM);
    proj_mma<<<dim3(S / 128, B * H, 3), 256, GEMM_SMEM>>>(Q, K, V, bq, bk, bv);

    // 2) attention (fp32)
    const int attn_smem = 4 * 64 * 65 * (int)sizeof(float);
    cudaFuncSetAttribute(attn_kernel, cudaFuncAttributeMaxDynamicSharedMemorySize, attn_smem);
    attn_kernel<<<dim3(S / 64, B * H), 256, attn_smem>>>();

    // 3) output projection on HMMA
    cudaFuncSetAttribute(oproj_mma, cudaFuncAttributeMaxDynamicSharedMemorySize, GEMM_SMEM);
    oproj_mma<<<dim3(512 / 64, 1024 / 128, B), 256, GEMM_SMEM>>>(bo, out);
}

// round 4
// speedup vs baseline: 3.2983x; 2.0972x over previous
#include <cuda_runtime.h>
#include <cuda_bf16.h>
#include <math.h>
#include <stdint.h>

// ---------------------------------------------------------------------------
// Problem constants
// ---------------------------------------------------------------------------
constexpr int B  = 8;
constexpr int S  = 1024;
constexpr int D  = 512;
constexpr int H  = 8;
constexpr int DH = 64;
constexpr int BHSD = B * H * S * DH;

// softmax scale folded into Q planes, in base-2 domain: 1/sqrt(64) * log2(e)
#define FOLD_F 0.18033688011112042f

// ---------------------------------------------------------------------------
// Device scratch
// ---------------------------------------------------------------------------
__device__ float g_X[BHSD];                 // attention output [b,h,s,dh] fp32

// bf16 hi/lo planes produced by the projections
__device__ __nv_bfloat16 g_Qbh[BHSD], g_Qbl[BHSD];   // [bh][s][dh], scale folded
__device__ __nv_bfloat16 g_Kbh[BHSD], g_Kbl[BHSD];   // [bh][s][dh]
__device__ __nv_bfloat16 g_Vth[BHSD], g_Vtl[BHSD];   // [bh][dh][s]  (transposed)

// Pre-transposed, bf16-split weight planes: [n][k] layout (k contiguous, ld=512)
__device__ __nv_bfloat16 g_Wt_hi [3 * H * DH * D];
__device__ __nv_bfloat16 g_Wt_lo [3 * H * DH * D];
__device__ __nv_bfloat16 g_Wot_hi[D * D];
__device__ __nv_bfloat16 g_Wot_lo[D * D];

// ---------------------------------------------------------------------------
// MMA / misc helpers
// ---------------------------------------------------------------------------
__device__ __forceinline__ void mma_bf16(float* d, const uint32_t* a, const uint32_t* b) {
    asm volatile(
        "mma.sync.aligned.m16n8k16.row.col.f32.bf16.bf16.f32 "
        "{%0,%1,%2,%3}, {%4,%5,%6,%7}, {%8,%9}, {%0,%1,%2,%3};"
        : "+f"(d[0]), "+f"(d[1]), "+f"(d[2]), "+f"(d[3])
        : "r"(a[0]), "r"(a[1]), "r"(a[2]), "r"(a[3]), "r"(b[0]), "r"(b[1]));
}

__device__ __forceinline__ float ex2f(float x) {
    float r;
    asm("ex2.approx.f32 %0, %1;" : "=f"(r) : "f"(x));
    return r;
}

#define CP_ASYNC16(dst_u32, gptr) \
    asm volatile("cp.async.cg.shared.global [%0], [%1], 16;" :: "r"(dst_u32), "l"(gptr))
#define CP_ASYNC_COMMIT() asm volatile("cp.async.commit_group;" ::: "memory")
#define CP_ASYNC_WAIT(n)  asm volatile("cp.async.wait_group %0;" :: "n"(n) : "memory")

__device__ __forceinline__ uint32_t pack_bf16x2(float a, float b, uint32_t& lo) {
    __nv_bfloat162 h = __floats2bfloat162_rn(a, b);
    float2 bk = __bfloat1622float2(h);
    __nv_bfloat162 l = __floats2bfloat162_rn(a - bk.x, b - bk.y);
    lo = *reinterpret_cast<uint32_t*>(&l);
    return *reinterpret_cast<uint32_t*>(&h);
}

// ---------------------------------------------------------------------------
// Weight prep: transpose + bf16 split
// ---------------------------------------------------------------------------
__global__ void prep_weights(const float* __restrict__ Wq,
                             const float* __restrict__ Wk,
                             const float* __restrict__ Wv,
                             const float* __restrict__ Wo)
{
    int idx = blockIdx.x * blockDim.x + threadIdx.x;   // 0 .. 1048575
    if (idx < 3 * H * DH * D) {
        int k = idx & 511;
        int e = (idx >> 9) & 63;
        int h = (idx >> 15) & 7;
        int p = idx >> 18;
        const float* W = (p == 0) ? Wq : (p == 1) ? Wk : Wv;
        float v = W[h * (D * DH) + k * DH + e];
        __nv_bfloat16 hi = __float2bfloat16(v);
        __nv_bfloat16 lo = __float2bfloat16(v - __bfloat162float(hi));
        g_Wt_hi[idx] = hi;
        g_Wt_lo[idx] = lo;
    } else {
        int j = idx - 3 * H * DH * D;                  // 0 .. 262143
        int k = j & 511;
        int n = j >> 9;
        float v = Wo[k * 512 + n];
        __nv_bfloat16 hi = __float2bfloat16(v);
        __nv_bfloat16 lo = __float2bfloat16(v - __bfloat162float(hi));
        g_Wot_hi[j] = hi;
        g_Wot_lo[j] = lo;
    }
}

// ---------------------------------------------------------------------------
// GEMM body: Out[128,64] = A[128,512](f32) * B[64,512](bf16 hi/lo)^T + bias
// mode 0: fp32 -> Out (ldOut)
// mode 1: bf16 hi/lo planes [s][64], value scaled by fold
// mode 2: bf16 hi/lo planes transposed [col][S], row offset sOff
// ---------------------------------------------------------------------------
constexpr int LDS_PAD = 72;
constexpr int GEMM_SMEM = (128 * LDS_PAD * 2 + 64 * LDS_PAD * 2) * 2;  // 55296

__device__ __forceinline__ void gemm_128x64_split(
    const float* __restrict__ A, int ldA,
    const __nv_bfloat16* __restrict__ Bh_g,
    const __nv_bfloat16* __restrict__ Bl_g,
    const float* __restrict__ bias,
    float* __restrict__ Out, int ldOut,
    char* smem,
    int mode, float fold,
    __nv_bfloat16* __restrict__ Oh, __nv_bfloat16* __restrict__ Ol,
    int sOff)
{
    __nv_bfloat16* As_hi = reinterpret_cast<__nv_bfloat16*>(smem);
    __nv_bfloat16* As_lo = As_hi + 128 * LDS_PAD;
    __nv_bfloat16* Bs_hi = As_lo + 128 * LDS_PAD;
    __nv_bfloat16* Bs_lo = Bs_hi + 64 * LDS_PAD;

    const int tid  = threadIdx.x;
    const int wid  = tid >> 5;
    const int lane = tid & 31;
    const int g    = lane >> 2;
    const int t    = lane & 3;
    const int m0   = (wid >> 1) * 32;
    const int n0w  = (wid & 1) * 32;

    float acc[2][4][4];
    #pragma unroll
    for (int mf = 0; mf < 2; mf++)
        #pragma unroll
        for (int nf = 0; nf < 4; nf++)
            #pragma unroll
            for (int r = 0; r < 4; r++) acc[mf][nf][r] = 0.f;

    for (int c = 0; c < 8; c++) {
        const int kk = c * 64;

        #pragma unroll
        for (int i = 0; i < 8; i++) {
            int idx = tid + i * 256;
            int row = idx >> 4, c4 = idx & 15;
            float4 v = *reinterpret_cast<const float4*>(A + (size_t)row * ldA + kk + c4 * 4);
            __nv_bfloat16 h0 = __float2bfloat16(v.x);
            __nv_bfloat16 h1 = __float2bfloat16(v.y);
            __nv_bfloat16 h2 = __float2bfloat16(v.z);
            __nv_bfloat16 h3 = __float2bfloat16(v.w);
            __nv_bfloat16 l0 = __float2bfloat16(v.x - __bfloat162float(h0));
            __nv_bfloat16 l1 = __float2bfloat16(v.y - __bfloat162float(h1));
            __nv_bfloat16 l2 = __float2bfloat16(v.z - __bfloat162float(h2));
            __nv_bfloat16 l3 = __float2bfloat16(v.w - __bfloat162float(h3));
            __nv_bfloat162 hp0 = __halves2bfloat162(h0, h1);
            __nv_bfloat162 hp1 = __halves2bfloat162(h2, h3);
            __nv_bfloat162 lp0 = __halves2bfloat162(l0, l1);
            __nv_bfloat162 lp1 = __halves2bfloat162(l2, l3);
            uint2 hw = make_uint2(*reinterpret_cast<uint32_t*>(&hp0),
                                  *reinterpret_cast<uint32_t*>(&hp1));
            uint2 lw = make_uint2(*reinterpret_cast<uint32_t*>(&lp0),
                                  *reinterpret_cast<uint32_t*>(&lp1));
            *reinterpret_cast<uint2*>(As_hi + row * LDS_PAD + c4 * 4) = hw;
            *reinterpret_cast<uint2*>(As_lo + row * LDS_PAD + c4 * 4) = lw;
        }

        #pragma unroll
        for (int i = 0; i < 2; i++) {
            int idx = tid + i * 256;
            int n = idx >> 3, q = idx & 7;
            *reinterpret_cast<uint4*>(Bs_hi + n * LDS_PAD + q * 8) =
                *reinterpret_cast<const uint4*>(Bh_g + (size_t)n * 512 + kk + q * 8);
            *reinterpret_cast<uint4*>(Bs_lo + n * LDS_PAD + q * 8) =
                *reinterpret_cast<const uint4*>(Bl_g + (size_t)n * 512 + kk + q * 8);
        }
        __syncthreads();

        #pragma unroll
        for (int ks = 0; ks < 4; ks++) {
            uint32_t ah[2][4], al[2][4];
            #pragma unroll
            for (int mf = 0; mf < 2; mf++) {
                int base = (m0 + mf * 16 + g) * LDS_PAD + ks * 16 + t * 2;
                ah[mf][0] = *reinterpret_cast<const uint32_t*>(As_hi + base);
                ah[mf][1] = *reinterpret_cast<const uint32_t*>(As_hi + base + 8 * LDS_PAD);
                ah[mf][2] = *reinterpret_cast<const uint32_t*>(As_hi + base + 8);
                ah[mf][3] = *reinterpret_cast<const uint32_t*>(As_hi + base + 8 * LDS_PAD + 8);
                al[mf][0] = *reinterpret_cast<const uint32_t*>(As_lo + base);
                al[mf][1] = *reinterpret_cast<const uint32_t*>(As_lo + base + 8 * LDS_PAD);
                al[mf][2] = *reinterpret_cast<const uint32_t*>(As_lo + base + 8);
                al[mf][3] = *reinterpret_cast<const uint32_t*>(As_lo + base + 8 * LDS_PAD + 8);
            }
            uint32_t bh[4][2], bl[4][2];
            #pragma unroll
            for (int nf = 0; nf < 4; nf++) {
                int base = (n0w + nf * 8 + g) * LDS_PAD + ks * 16 + t * 2;
                bh[nf][0] = *reinterpret_cast<const uint32_t*>(Bs_hi + base);
                bh[nf][1] = *reinterpret_cast<const uint32_t*>(Bs_hi + base + 8);
                bl[nf][0] = *reinterpret_cast<const uint32_t*>(Bs_lo + base);
                bl[nf][1] = *reinterpret_cast<const uint32_t*>(Bs_lo + base + 8);
            }
            #pragma unroll
            for (int mf = 0; mf < 2; mf++)
                #pragma unroll
                for (int nf = 0; nf < 4; nf++) {
                    mma_bf16(acc[mf][nf], ah[mf], bh[nf]);
                    mma_bf16(acc[mf][nf], ah[mf], bl[nf]);
                    mma_bf16(acc[mf][nf], al[mf], bh[nf]);
                }
        }
        __syncthreads();
    }

    // ---- epilogue ----
    #pragma unroll
    for (int mf = 0; mf < 2; mf++) {
        #pragma unroll
        for (int nf = 0; nf < 4; nf++) {
            int row = m0 + mf * 16 + g;
            int col = n0w + nf * 8 + t * 2;
            float b0 = bias[col], b1 = bias[col + 1];
            float v00 = acc[mf][nf][0] + b0, v01 = acc[mf][nf][1] + b1;
            float v10 = acc[mf][nf][2] + b0, v11 = acc[mf][nf][3] + b1;
            if (mode == 0) {
                *reinterpret_cast<float2*>(Out + (size_t)row * ldOut + col) =
                    make_float2(v00, v01);
                *reinterpret_cast<float2*>(Out + (size_t)(row + 8) * ldOut + col) =
                    make_float2(v10, v11);
            } else if (mode == 1) {
                v00 *= fold; v01 *= fold; v10 *= fold; v11 *= fold;
                uint32_t lo0, lo1;
                uint32_t hi0 = pack_bf16x2(v00, v01, lo0);
                uint32_t hi1 = pack_bf16x2(v10, v11, lo1);
                *reinterpret_cast<uint32_t*>(Oh + (size_t)row * 64 + col) = hi0;
                *reinterpret_cast<uint32_t*>(Ol + (size_t)row * 64 + col) = lo0;
                *reinterpret_cast<uint32_t*>(Oh + (size_t)(row + 8) * 64 + col) = hi1;
                *reinterpret_cast<uint32_t*>(Ol + (size_t)(row + 8) * 64 + col) = lo1;
            } else {
                // transposed planes [col][S]
                float vv[4] = {v00, v01, v10, v11};
                int rr[4] = {row, row, row + 8, row + 8};
                int cc[4] = {col, col + 1, col, col + 1};
                #pragma unroll
                for (int q = 0; q < 4; q++) {
                    __nv_bfloat16 hi = __float2bfloat16(vv[q]);
                    __nv_bfloat16 lo = __float2bfloat16(vv[q] - __bfloat162float(hi));
                    size_t a = (size_t)cc[q] * S + sOff + rr[q];
                    Oh[a] = hi;
                    Ol[a] = lo;
                }
            }
        }
    }
}

// ---------------------------------------------------------------------------
// QKV projection: grid (S/128, B*H, 3), block 256
// ---------------------------------------------------------------------------
__global__ void __launch_bounds__(256)
proj_mma(const float* __restrict__ Q, const float* __restrict__ K,
         const float* __restrict__ V,
         const float* __restrict__ bq, const float* __restrict__ bk,
         const float* __restrict__ bv)
{
    extern __shared__ char smem[];
    const int p  = blockIdx.z;
    const int bh = blockIdx.y;
    const int b  = bh >> 3, h = bh & 7;
    const int s0 = blockIdx.x * 128;

    const float* In   = (p == 0) ? Q : (p == 1) ? K : V;
    const float* bias = ((p == 0) ? bq : (p == 1) ? bk : bv) + h * DH;
    const size_t hb = (size_t)bh * S * DH;

    const float* Ab = In + ((size_t)b * S + s0) * D;
    const __nv_bfloat16* Wh = g_Wt_hi + (size_t)(p * H + h) * DH * D;
    const __nv_bfloat16* Wl = g_Wt_lo + (size_t)(p * H + h) * DH * D;

    if (p == 0) {
        gemm_128x64_split(Ab, D, Wh, Wl, bias, nullptr, 0, smem,
                          1, FOLD_F, g_Qbh + hb + (size_t)s0 * 64,
                          g_Qbl + hb + (size_t)s0 * 64, 0);
    } else if (p == 1) {
        gemm_128x64_split(Ab, D, Wh, Wl, bias, nullptr, 0, smem,
                          1, 1.0f, g_Kbh + hb + (size_t)s0 * 64,
                          g_Kbl + hb + (size_t)s0 * 64, 0);
    } else {
        gemm_128x64_split(Ab, D, Wh, Wl, bias, nullptr, 0, smem,
                          2, 1.0f, g_Vth + hb, g_Vtl + hb, s0);
    }
}

// ---------------------------------------------------------------------------
// Output projection: grid (512/64, 1024/128, B), block 256
// ---------------------------------------------------------------------------
__global__ void __launch_bounds__(256)
oproj_mma(const float* __restrict__ bo, float* __restrict__ out)
{
    extern __shared__ char smem[];
    const int b  = blockIdx.z;
    const int m0 = blockIdx.y * 128;
    const int n0 = blockIdx.x * 64;

    gemm_128x64_split(g_X + (size_t)b * 1024 * 512 + (size_t)m0 * 512, 512,
                      g_Wot_hi + (size_t)n0 * D,
                      g_Wot_lo + (size_t)n0 * D,
                      bo + n0,
                      out + (size_t)b * 1024 * 512 + (size_t)m0 * 512 + n0, 512,
                      smem, 0, 1.0f, nullptr, nullptr, 0);
}

// ---------------------------------------------------------------------------
// Flash attention on HMMA bf16 split.
// grid (S/64 = 16, B*H = 64), block 128 (4 warps, 16 Q rows each).
// smem: double-buffered {Kh, Kl, Vth, Vtl} tiles of [64][72] bf16.
// ---------------------------------------------------------------------------
constexpr int SPAD  = 72;
constexpr int PLANE = 64 * SPAD;           // elems
constexpr int ABUF  = 4 * PLANE;           // elems per buffer
constexpr int ATTN_SMEM = 2 * ABUF * 2;    // bytes = 73728

__device__ __forceinline__ void attn_issue_tile(
    const __nv_bfloat16* Khp, const __nv_bfloat16* Klp,
    const __nv_bfloat16* Vhp, const __nv_bfloat16* Vlp,
    __nv_bfloat16* sbuf, int kv0, int tid)
{
    #pragma unroll
    for (int i = 0; i < 4; i++) {
        int idx = tid + i * 128;           // 0..511
        int row = idx >> 3, c = (idx & 7) * 8;
        uint32_t d0 = (uint32_t)__cvta_generic_to_shared(sbuf + row * SPAD + c);
        CP_ASYNC16(d0, Khp + (size_t)(kv0 + row) * 64 + c);
        uint32_t d1 = (uint32_t)__cvta_generic_to_shared(sbuf + PLANE + row * SPAD + c);
        CP_ASYNC16(d1, Klp + (size_t)(kv0 + row) * 64 + c);
        uint32_t d2 = (uint32_t)__cvta_generic_to_shared(sbuf + 2 * PLANE + row * SPAD + c);
        CP_ASYNC16(d2, Vhp + (size_t)row * S + kv0 + c);
        uint32_t d3 = (uint32_t)__cvta_generic_to_shared(sbuf + 3 * PLANE + row * SPAD + c);
        CP_ASYNC16(d3, Vlp + (size_t)row * S + kv0 + c);
    }
    CP_ASYNC_COMMIT();
}

__global__ void __launch_bounds__(128, 3) attn_mma()
{
    extern __shared__ __nv_bfloat16 smatt[];
    const int tid  = threadIdx.x;
    const int w    = tid >> 5;
    const int lane = tid & 31;
    const int g    = lane >> 2;
    const int t    = lane & 3;
    const int bh   = blockIdx.y;
    const int q0   = blockIdx.x * 64;
    const size_t hb = (size_t)bh * S * DH;

    const __nv_bfloat16* Qhp = g_Qbh + hb;
    const __nv_bfloat16* Qlp = g_Qbl + hb;
    const __nv_bfloat16* Khp = g_Kbh + hb;
    const __nv_bfloat16* Klp = g_Kbl + hb;
    const __nv_bfloat16* Vhp = g_Vth + hb;
    const __nv_bfloat16* Vlp = g_Vtl + hb;

    // Q fragments, resident in registers (scale*log2e already folded in)
    uint32_t qh[4][4], ql[4][4];
    const int r0 = q0 + w * 16 + g;
    #pragma unroll
    for (int ks = 0; ks < 4; ks++) {
        int c0 = ks * 16 + 2 * t;
        qh[ks][0] = *reinterpret_cast<const uint32_t*>(Qhp + (size_t)r0 * 64 + c0);
        qh[ks][1] = *reinterpret_cast<const uint32_t*>(Qhp + (size_t)(r0 + 8) * 64 + c0);
        qh[ks][2] = *reinterpret_cast<const uint32_t*>(Qhp + (size_t)r0 * 64 + c0 + 8);
        qh[ks][3] = *reinterpret_cast<const uint32_t*>(Qhp + (size_t)(r0 + 8) * 64 + c0 + 8);
        ql[ks][0] = *reinterpret_cast<const uint32_t*>(Qlp + (size_t)r0 * 64 + c0);
        ql[ks][1] = *reinterpret_cast<const uint32_t*>(Qlp + (size_t)(r0 + 8) * 64 + c0);
        ql[ks][2] = *reinterpret_cast<const uint32_t*>(Qlp + (size_t)r0 * 64 + c0 + 8);
        ql[ks][3] = *reinterpret_cast<const uint32_t*>(Qlp + (size_t)(r0 + 8) * 64 + c0 + 8);
    }

    float O[8][4];
    #pragma unroll
    for (int nf = 0; nf < 8; nf++)
        #pragma unroll
        for (int r = 0; r < 4; r++) O[nf][r] = 0.f;
    float ma = -INFINITY, mb = -INFINITY, la = 0.f, lb = 0.f;

    attn_issue_tile(Khp, Klp, Vhp, Vlp, smatt, 0, tid);

    for (int kt = 0; kt < 16; kt++) {
        const int bb = kt & 1;
        if (kt + 1 < 16) {
            attn_issue_tile(Khp, Klp, Vhp, Vlp, smatt + (1 - bb) * ABUF,
                            (kt + 1) * 64, tid);
            CP_ASYNC_WAIT(1);
        } else {
            CP_ASYNC_WAIT(0);
        }
        __syncthreads();

        const __nv_bfloat16* sb = smatt + bb * ABUF;

        // ---- scores (base-2 domain) ----
        float sc[8][4];
        #pragma unroll
        for (int nf = 0; nf < 8; nf++)
            #pragma unroll
            for (int r = 0; r < 4; r++) sc[nf][r] = 0.f;

        #pragma unroll
        for (int ks = 0; ks < 4; ks++) {
            uint32_t kh[8][2], kl[8][2];
            #pragma unroll
            for (int nf = 0; nf < 8; nf++) {
                int base = (nf * 8 + g) * SPAD + ks * 16 + 2 * t;
                kh[nf][0] = *reinterpret_cast<const uint32_t*>(sb + base);
                kh[nf][1] = *reinterpret_cast<const uint32_t*>(sb + base + 8);
                kl[nf][0] = *reinterpret_cast<const uint32_t*>(sb + PLANE + base);
                kl[nf][1] = *reinterpret_cast<const uint32_t*>(sb + PLANE + base + 8);
            }
            #pragma unroll
            for (int nf = 0; nf < 8; nf++) {
                mma_bf16(sc[nf], qh[ks], kh[nf]);
                mma_bf16(sc[nf], qh[ks], kl[nf]);
                mma_bf16(sc[nf], ql[ks], kh[nf]);
            }
        }

        // ---- online softmax ----
        float mxa = sc[0][0], mxb = sc[0][2];
        #pragma unroll
        for (int nf = 0; nf < 8; nf++) {
            mxa = fmaxf(mxa, fmaxf(sc[nf][0], sc[nf][1]));
            mxb = fmaxf(mxb, fmaxf(sc[nf][2], sc[nf][3]));
        }
        mxa = fmaxf(mxa, __shfl_xor_sync(0xffffffffu, mxa, 1));
        mxa = fmaxf(mxa, __shfl_xor_sync(0xffffffffu, mxa, 2));
        mxb = fmaxf(mxb, __shfl_xor_sync(0xffffffffu, mxb, 1));
        mxb = fmaxf(mxb, __shfl_xor_sync(0xffffffffu, mxb, 2));
        float mna = fmaxf(ma, mxa), mnb = fmaxf(mb, mxb);
        float aa = ex2f(ma - mna), ab = ex2f(mb - mnb);
        ma = mna; mb = mnb;
        float rsa = 0.f, rsb = 0.f;
        #pragma unroll
        for (int nf = 0; nf < 8; nf++) {
            sc[nf][0] = ex2f(sc[nf][0] - mna);
            sc[nf][1] = ex2f(sc[nf][1] - mna);
            sc[nf][2] = ex2f(sc[nf][2] - mnb);
            sc[nf][3] = ex2f(sc[nf][3] - mnb);
            rsa += sc[nf][0] + sc[nf][1];
            rsb += sc[nf][2] + sc[nf][3];
        }
        rsa += __shfl_xor_sync(0xffffffffu, rsa, 1);
        rsa += __shfl_xor_sync(0xffffffffu, rsa, 2);
        rsb += __shfl_xor_sync(0xffffffffu, rsb, 1);
        rsb += __shfl_xor_sync(0xffffffffu, rsb, 2);
        la = la * aa + rsa;
        lb = lb * ab + rsb;
        #pragma unroll
        for (int nf = 0; nf < 8; nf++) {
            O[nf][0] *= aa; O[nf][1] *= aa;
            O[nf][2] *= ab; O[nf][3] *= ab;
        }

        // ---- P @ V ----
        #pragma unroll
        for (int ks = 0; ks < 4; ks++) {
            uint32_t ph[4], pl[4];
            ph[0] = pack_bf16x2(sc[2 * ks][0],     sc[2 * ks][1],     pl[0]);
            ph[1] = pack_bf16x2(sc[2 * ks][2],     sc[2 * ks][3],     pl[1]);
            ph[2] = pack_bf16x2(sc[2 * ks + 1][0], sc[2 * ks + 1][1], pl[2]);
            ph[3] = pack_bf16x2(sc[2 * ks + 1][2], sc[2 * ks + 1][3], pl[3]);

            uint32_t vh[8][2], vl[8][2];
            #pragma unroll
            for (int nf = 0; nf < 8; nf++) {
                int base = (nf * 8 + g) * SPAD + ks * 16 + 2 * t;
                vh[nf][0] = *reinterpret_cast<const uint32_t*>(sb + 2 * PLANE + base);
                vh[nf][1] = *reinterpret_cast<const uint32_t*>(sb + 2 * PLANE + base + 8);
                vl[nf][0] = *reinterpret_cast<const uint32_t*>(sb + 3 * PLANE + base);
                vl[nf][1] = *reinterpret_cast<const uint32_t*>(sb + 3 * PLANE + base + 8);
            }
            #pragma unroll
            for (int nf = 0; nf < 8; nf++) {
                mma_bf16(O[nf], ph, vh[nf]);
                mma_bf16(O[nf], ph, vl[nf]);
                mma_bf16(O[nf], pl, vh[nf]);
            }
        }
        __syncthreads();
    }

    // ---- epilogue ----
    float ia = 1.0f / la, ib = 1.0f / lb;
    float* X = g_X + hb;
    #pragma unroll
    for (int nf = 0; nf < 8; nf++) {
        int c = nf * 8 + 2 * t;
        *reinterpret_cast<float2*>(X + (size_t)r0 * 64 + c) =
            make_float2(O[nf][0] * ia, O[nf][1] * ia);
        *reinterpret_cast<float2*>(X + (size_t)(r0 + 8) * 64 + c) =
            make_float2(O[nf][2] * ib, O[nf][3] * ib);
    }
}

// ---------------------------------------------------------------------------
extern "C" void kernel_launch(void* const* d_in, const int* in_sizes, int n_in,
                              void* d_out, int out_size)
{
    const float* Q  = (const float*)d_in[0];
    const float* K  = (const float*)d_in[1];
    const float* V  = (const float*)d_in[2];
    const float* Wq = (const float*)d_in[3];
    const float* bq = (const float*)d_in[4];
    const float* Wk = (const float*)d_in[5];
    const float* bk = (const float*)d_in[6];
    const float* Wv = (const float*)d_in[7];
    const float* bv = (const float*)d_in[8];
    const float* Wo = (const float*)d_in[9];
    const float* bo = (const float*)d_in[10];
    float* out = (float*)d_out;

    // 0) weight transpose + bf16 split
    prep_weights<<<4096, 256>>>(Wq, Wk, Wv, Wo);

    // 1) QKV projections -> bf16 hi/lo planes
    cudaFuncSetAttribute(proj_mma, cudaFuncAttributeMaxDynamicSharedMemorySize, GEMM_SMEM);
    proj_mma<<<dim3(S / 128, B * H, 3), 256, GEMM_SMEM>>>(Q, K, V, bq, bk, bv);

    // 2) attention on HMMA
    cudaFuncSetAttribute(attn_mma, cudaFuncAttributeMaxDynamicSharedMemorySize, ATTN_SMEM);
    attn_mma<<<dim3(S / 64, B * H), 128, ATTN_SMEM>>>();

    // 3) output projection
    cudaFuncSetAttribute(oproj_mma, cudaFuncAttributeMaxDynamicSharedMemorySize, GEMM_SMEM);
    oproj_mma<<<dim3(512 / 64, 1024 / 128, B), 256, GEMM_SMEM>>>(bo, out);
}